// round 2
// baseline (speedup 1.0000x reference)
#include <cuda_runtime.h>

// RoiPooling: crop_and_resize(img[0], 2048 boxes, crop=7) over 512 channels.
// Separable bilinear with per-row x-interp register cache + uniform dedupe.
// img: (16,28,28,512) f32 -> only img[0] used. rois: 2048 boxes of 5 floats,
// x1 = r[5n+3], y1 = r[5n+4], window = 4/28. Coords guaranteed >= 0.
// out: (2048,7,7,512) f32 linear.

#define IMG_H 28
#define IMG_W 28
#define IMG_C 512
#define POOLN 7
#define NBOX 2048

// x-interpolate one image row into xv[0..6]. Branches are uniform per CTA.
// Two-entry marching cache: column indices are nondecreasing with step <= 1,
// so each unique column is loaded exactly once (~5-6 loads instead of 14).
#define XROW(rowbase, xv) do {                                              \
    int iA = -1, iB = -1; float vA = 0.f, vB = 0.f;                         \
    _Pragma("unroll")                                                       \
    for (int j = 0; j < POOLN; j++) {                                       \
        int a0 = min(ax[j], IMG_W - 1);                                     \
        int b0 = min(ax[j] + 1, IMG_W - 1);                                 \
        float c0 = (a0 == iB) ? vB                                          \
                 : ((a0 == iA) ? vA : __ldg((rowbase) + a0 * IMG_C));       \
        float c1 = (b0 == a0) ? c0                                          \
                 : ((b0 == iB) ? vB : __ldg((rowbase) + b0 * IMG_C));       \
        iA = a0; vA = c0; iB = b0; vB = c1;                                 \
        (xv)[j] = c0 + (c1 - c0) * lx[j];                                   \
    }                                                                       \
} while (0)

__global__ __launch_bounds__(512, 2) void roi_pool_kernel(
    const float* __restrict__ img,
    const float* __restrict__ rois,
    float* __restrict__ out)
{
    const int box = blockIdx.x;
    const int c = threadIdx.x;              // channel 0..511

    const float x1 = rois[box * 5 + 3];
    const float y1 = rois[box * 5 + 4];
    const float win = (float)(4.0 / 28.0);
    // Match JAX numerics: (x2-x1)*(W-1)/(crop-1) in f32
    const float sx = (((x1 + win) - x1) * 27.0f) / 6.0f;
    const float sy = (((y1 + win) - y1) * 27.0f) / 6.0f;
    const float fx = x1 * 27.0f;
    const float fy = y1 * 27.0f;

    // Per-column fractions + floor indices (coords >= 0 always)
    float lx[POOLN];
    int ax[POOLN];
#pragma unroll
    for (int j = 0; j < POOLN; j++) {
        float xs = fx + (float)j * sx;
        float xf = floorf(xs);
        lx[j] = xs - xf;
        ax[j] = (int)xf;                    // >= 0
    }

    const float* base = img + c;            // channel-offset base, stride IMG_C per pixel
    float* outp = out + ((size_t)box * (POOLN * POOLN)) * IMG_C + c;

    // 2-row x-interp cache
    float xvA[POOLN], xvB[POOLN];
    int cy0 = -100, cy1 = -100;

#pragma unroll
    for (int i = 0; i < POOLN; i++) {
        float ys = fy + (float)i * sy;
        float yf = floorf(ys);
        float ly = ys - yf;
        int ya = (int)yf;                   // >= 0
        int y0 = min(ya, IMG_H - 1);
        int yb = min(ya + 1, IMG_H - 1);
        float my = (ys <= 27.0f) ? 1.0f : 0.0f;

        // Ensure cache holds rows (y0, yb). Rows are nondecreasing, step <= 1.
        if (y0 != cy0) {
            if (y0 == cy1) {                // shift bottom -> top
#pragma unroll
                for (int j = 0; j < POOLN; j++) xvA[j] = xvB[j];
            } else {
                const float* row = base + (size_t)y0 * IMG_W * IMG_C;
                XROW(row, xvA);
            }
            cy0 = y0;
        }
        if (yb != cy1) {
            if (yb == cy0) {                // clamped: both rows identical
#pragma unroll
                for (int j = 0; j < POOLN; j++) xvB[j] = xvA[j];
            } else {
                const float* row = base + (size_t)yb * IMG_W * IMG_C;
                XROW(row, xvB);
            }
            cy1 = yb;
        }

        float omly = 1.0f - ly;
#pragma unroll
        for (int j = 0; j < POOLN; j++) {
            // mask: xs = ax[j] + lx[j] exactly; valid iff xs <= 27
            float mx = (((float)ax[j] + lx[j]) <= 27.0f) ? 1.0f : 0.0f;
            float v = (xvA[j] * omly + xvB[j] * ly) * (my * mx);
            outp[(i * POOLN + j) * IMG_C] = v;
        }
    }
}

extern "C" void kernel_launch(void* const* d_in, const int* in_sizes, int n_in,
                              void* d_out, int out_size) {
    const float* img  = (const float*)d_in[0];
    const float* rois = (const float*)d_in[1];
    float* out = (float*)d_out;
    (void)in_sizes; (void)n_in; (void)out_size;
    roi_pool_kernel<<<NBOX, 512>>>(img, rois, out);
}

// round 3
// speedup vs baseline: 1.8783x; 1.8783x over previous
#include <cuda_runtime.h>

// RoiPooling: crop_and_resize(img[0], 2048 boxes, crop=7) over 512 channels.
// Separable bilinear. Per image row: 6 independent float4 loads of the unique
// columns x_lo..x_lo+5, then compile-time-indexed predicated selects pick each
// sample's corners (BASE[j] pattern from the fixed window 4/28). Rolling 2-row
// x-interp cache in the y direction (CTA-uniform branches). No serial chains.

#define IMG_H 28
#define IMG_W 28
#define C4    128          // 512 channels / 4
#define POOLN 7
#define NBOX  2048
#define ROWSTRIDE (IMG_W * C4)   // float4 elems per image row

// x-interp one image row (given float4-elem offset `rowofs`) into xv[0..6].
// BASE[j] is compile-time; cond[] selects are CTA-uniform.
#define XROW(rowofs, xv) do {                                                 \
    float4 p[6];                                                              \
    _Pragma("unroll")                                                         \
    for (int k = 0; k < 6; k++)                                               \
        p[k] = __ldg(base_img + (rowofs) + colofs[k]);                        \
    _Pragma("unroll")                                                         \
    for (int j = 0; j < POOLN; j++) {                                         \
        const int b = BASE_X[j];                                              \
        float4 c0, c1;                                                        \
        if (cond[j]) { c0 = p[b + 1]; c1 = p[b + 2]; }                        \
        else         { c0 = p[b];     c1 = p[b + 1]; }                        \
        float l = lx[j];                                                      \
        (xv)[j].x = c0.x + (c1.x - c0.x) * l;                                 \
        (xv)[j].y = c0.y + (c1.y - c0.y) * l;                                 \
        (xv)[j].z = c0.z + (c1.z - c0.z) * l;                                 \
        (xv)[j].w = c0.w + (c1.w - c0.w) * l;                                 \
    }                                                                         \
} while (0)

__global__ __launch_bounds__(128, 4) void roi_pool_kernel(
    const float4* __restrict__ img4,   // img[0] as float4: (28*28, 128)
    const float*  __restrict__ rois,
    float4* __restrict__ out4)
{
    // floor(j * 27*4/(28*6)) for j=0..6; j*sx is >=0.07 from any integer,
    // far beyond f32 rounding wiggle in sx, so ax[j]-ax[0] ∈ {BASE,BASE+1}.
    const int BASE_X[POOLN] = {0, 0, 1, 1, 2, 3, 3};

    const int box = blockIdx.x;
    const int tid = threadIdx.x;           // channel-quad 0..127

    const float x1 = rois[box * 5 + 3];
    const float y1 = rois[box * 5 + 4];
    const float win = (float)(4.0 / 28.0);
    // Match JAX numerics exactly: ((x1+win)-x1)*27/6 in f32
    const float sx = (((x1 + win) - x1) * 27.0f) / 6.0f;
    const float sy = (((y1 + win) - y1) * 27.0f) / 6.0f;
    const float fx = x1 * 27.0f;
    const float fy = y1 * 27.0f;

    const int x_lo = (int)floorf(fx);      // rois >= 0 so fx >= 0

    float lx[POOLN], mx[POOLN];
    bool cond[POOLN];
#pragma unroll
    for (int j = 0; j < POOLN; j++) {
        float xs = fx + (float)j * sx;
        float xf = floorf(xs);
        lx[j] = xs - xf;
        int ax = (int)xf;
        cond[j] = (ax - x_lo) > BASE_X[j];
        mx[j] = (xs <= 27.0f) ? 1.0f : 0.0f;
    }

    // Unique-column offsets (clamped, always in-bounds)
    int colofs[6];
#pragma unroll
    for (int k = 0; k < 6; k++)
        colofs[k] = min(x_lo + k, IMG_W - 1) * C4;

    const float4* base_img = img4 + tid;
    float4* outp = out4 + (size_t)box * (POOLN * POOLN) * C4 + tid;

    float4 xvA[POOLN], xvB[POOLN];
    int cy0 = -1000, cy1 = -1000;

#pragma unroll
    for (int i = 0; i < POOLN; i++) {
        float ys = fy + (float)i * sy;
        float yf = floorf(ys);
        float ly = ys - yf;
        int ya = (int)yf;
        int y0 = min(ya, IMG_H - 1);
        int yb = min(ya + 1, IMG_H - 1);
        float my = (ys <= 27.0f) ? 1.0f : 0.0f;

        if (y0 != cy0) {
            if (y0 == cy1) {
#pragma unroll
                for (int j = 0; j < POOLN; j++) xvA[j] = xvB[j];
            } else {
                XROW(y0 * ROWSTRIDE, xvA);
            }
            cy0 = y0;
        }
        if (yb != cy1) {
            if (yb == cy0) {
#pragma unroll
                for (int j = 0; j < POOLN; j++) xvB[j] = xvA[j];
            } else {
                XROW(yb * ROWSTRIDE, xvB);
            }
            cy1 = yb;
        }

        float omly = 1.0f - ly;
#pragma unroll
        for (int j = 0; j < POOLN; j++) {
            float m = my * mx[j];
            float4 v;
            v.x = (xvA[j].x * omly + xvB[j].x * ly) * m;
            v.y = (xvA[j].y * omly + xvB[j].y * ly) * m;
            v.z = (xvA[j].z * omly + xvB[j].z * ly) * m;
            v.w = (xvA[j].w * omly + xvB[j].w * ly) * m;
            __stcs(outp + (i * POOLN + j) * C4, v);
        }
    }
}

extern "C" void kernel_launch(void* const* d_in, const int* in_sizes, int n_in,
                              void* d_out, int out_size) {
    const float* img  = (const float*)d_in[0];
    const float* rois = (const float*)d_in[1];
    float* out = (float*)d_out;
    (void)in_sizes; (void)n_in; (void)out_size;
    roi_pool_kernel<<<NBOX, 128>>>((const float4*)img, rois, (float4*)out);
}